// round 2
// baseline (speedup 1.0000x reference)
#include <cuda_runtime.h>
#include <cuda_bf16.h>
#include <stdint.h>

// ============================================================================
// Problem constants
// ============================================================================
#define NROWS 8192
#define DIMK  256
#define NLBL  1024
#define NSPLIT 2                       // column splits
#define COLS_PER_CTA (NROWS / NSPLIT)  // 4096
#define TTILES (COLS_PER_CTA / 128)    // 32
#define TEMP_INV 14.285714285714286f   // 1/0.07
// exp((d-1)/T) = 2^(d*K - K), K = (1/T)*log2(e)
#define K_EX2 20.609929191666664f

// ============================================================================
// Device scratch (no allocation allowed)
// ============================================================================
__device__ __align__(128) __nv_bfloat16 g_en[NROWS * DIMK];  // normalized rows, bf16
__device__ int   g_lbl[NROWS];
__device__ int   g_hist[NLBL];
__device__ int   g_is64;
__device__ float g_S[2 * NSPLIT][NROWS];  // partial exp-sums per (split, col-half)
__device__ float g_P[2 * NSPLIT][NROWS];  // partial positive-sim sums

// ============================================================================
// PTX helpers (baseline sm_80+ only — target is compute_103 WITHOUT 'a')
// ============================================================================
__device__ __forceinline__ uint32_t smem_u32(const void* p) {
    uint32_t a;
    asm("{ .reg .u64 t; cvta.to.shared.u64 t, %1; cvt.u32.u64 %0, t; }" : "=r"(a) : "l"(p));
    return a;
}

__device__ __forceinline__ void cp16(uint32_t dst, const void* src) {
    asm volatile("cp.async.cg.shared.global [%0], [%1], 16;" :: "r"(dst), "l"(src));
}
#define CP_COMMIT() asm volatile("cp.async.commit_group;" ::: "memory")
#define CP_WAIT1()  asm volatile("cp.async.wait_group 1;" ::: "memory")
#define CP_WAIT0()  asm volatile("cp.async.wait_group 0;" ::: "memory")

__device__ __forceinline__ void ldsm4(uint32_t* r, uint32_t addr) {
    asm volatile("ldmatrix.sync.aligned.m8n8.x4.shared.b16 {%0,%1,%2,%3}, [%4];"
        : "=r"(r[0]), "=r"(r[1]), "=r"(r[2]), "=r"(r[3]) : "r"(addr));
}

__device__ __forceinline__ void mma16816(float* d, const uint32_t* a, const uint32_t* b) {
    asm volatile(
        "mma.sync.aligned.m16n8k16.row.col.f32.bf16.bf16.f32 "
        "{%0,%1,%2,%3}, {%4,%5,%6,%7}, {%8,%9}, {%0,%1,%2,%3};"
        : "+f"(d[0]), "+f"(d[1]), "+f"(d[2]), "+f"(d[3])
        : "r"(a[0]), "r"(a[1]), "r"(a[2]), "r"(a[3]), "r"(b[0]), "r"(b[1]));
}

__device__ __forceinline__ float ex2f(float x) {
    float e;
    asm("ex2.approx.f32 %0, %1;" : "=f"(e) : "f"(x));
    return e;
}

// ============================================================================
// SMEM layout (padded K-major tiles: 128 rows x 264 bf16 -> 528 B row stride;
// 33 chunks of 16B per row, odd -> conflict-free ldmatrix over 8-row strides)
// ============================================================================
#define ROWB   528
#define TILEB  (128 * ROWB)                // 67584
#define SOFF_A   0
#define SOFF_B0  TILEB
#define SOFF_B1  (2 * TILEB)
#define SOFF_LBL (3 * TILEB)               // 202752
#define SMEM_TOTAL (SOFF_LBL + 128 * 4)    // 203264

// Fill one 128-row x 256-col bf16 tile via cp.async (32 chunks/row, pad chunk unused)
__device__ __forceinline__ void load_tile(uint32_t dst_base, int grow_base, int tid) {
    #pragma unroll
    for (int i = 0; i < 16; i++) {
        int c = tid + i * 256;     // 0..4095
        int r = c >> 5;            // row
        int q = c & 31;            // 16B chunk
        cp16(dst_base + r * ROWB + q * 16,
             (const void*)(g_en + (size_t)(grow_base + r) * DIMK + q * 8));
    }
}

// ============================================================================
// Kernel 1: zero histogram
// ============================================================================
__global__ void zero_kernel() {
    if (threadIdx.x < NLBL) g_hist[threadIdx.x] = 0;
}

// ============================================================================
// Kernel 2: detect labels dtype (int64 vs int32)
// ============================================================================
__global__ void detect_kernel(const int* lab32) {
    __shared__ int any;
    if (threadIdx.x == 0) any = 0;
    __syncthreads();
    for (int i = threadIdx.x; i < 4096; i += blockDim.x)
        if (lab32[2 * i + 1] != 0) any = 1;  // benign race
    __syncthreads();
    if (threadIdx.x == 0) g_is64 = (any == 0) ? 1 : 0;
}

// ============================================================================
// Kernel 3: normalize rows -> bf16, labels -> int32, histogram
// ============================================================================
__global__ void prep_kernel(const float* __restrict__ emb, const void* __restrict__ labels) {
    int row = blockIdx.x;
    int tid = threadIdx.x;  // 256 threads = 1 per element
    float v = emb[(size_t)row * DIMK + tid];
    float ss = v * v;
    #pragma unroll
    for (int o = 16; o; o >>= 1) ss += __shfl_xor_sync(0xffffffffu, ss, o);
    __shared__ float ws[8];
    if ((tid & 31) == 0) ws[tid >> 5] = ss;
    __syncthreads();
    float tot = ws[0] + ws[1] + ws[2] + ws[3] + ws[4] + ws[5] + ws[6] + ws[7];
    float inv = 1.0f / fmaxf(sqrtf(tot), 1e-12f);
    g_en[(size_t)row * DIMK + tid] = __float2bfloat16(v * inv);
    if (tid == 0) {
        int l = g_is64 ? (int)((const long long*)labels)[row] : ((const int*)labels)[row];
        g_lbl[row] = l;
        atomicAdd(&g_hist[l], 1);
    }
}

// ============================================================================
// Kernel 4: fused bf16 mma.sync GEMM + online exp-sum / positive-sum epilogue
// Grid (NSPLIT, 64), 256 threads = 8 warps.
// Warp tiling of the 128x128 output tile: warpM = wid&3 (32 rows), warpN = wid>>2 (64 cols)
// ============================================================================
__global__ void __launch_bounds__(256, 1) gemm_kernel() {
    extern __shared__ char smem[];
    uint32_t sb = smem_u32(smem);
    int tid = threadIdx.x, wid = tid >> 5, lid = tid & 31;
    int warpM = wid & 3, warpN = wid >> 2;
    int split = blockIdx.x, rtile = blockIdx.y;
    int row_base = rtile * 128;
    int split_base = split * COLS_PER_CTA;
    int* lbl_s = (int*)(smem + SOFF_LBL);

    // Per-lane fixed row info: 4 rows = row_base + warpM*32 + mf*16 + hi*8 + lid/4
    int rowg[4], myl[4];
    #pragma unroll
    for (int idx = 0; idx < 4; idx++) {
        int mf = idx >> 1, hi = idx & 1;
        rowg[idx] = row_base + warpM * 32 + mf * 16 + hi * 8 + (lid >> 2);
        myl[idx] = g_lbl[rowg[idx]];
    }

    // ldmatrix per-lane base addresses (see fragment-mapping derivation)
    uint32_t aAddr = sb + SOFF_A
        + (uint32_t)(warpM * 32 + (lid & 7) + ((lid >> 3) & 1) * 8) * ROWB
        + ((lid >> 4) & 1) * 16;
    uint32_t bOff =
        (uint32_t)(warpN * 64 + (lid & 7) + ((lid >> 4) & 1) * 8) * ROWB
        + ((lid >> 3) & 1) * 16;

    // Prologue: A tile + B tile 0 as one cp.async group
    load_tile(sb + SOFF_A, row_base, tid);
    load_tile(sb + SOFF_B0, split_base, tid);
    CP_COMMIT();

    float Sa[4] = {0.f, 0.f, 0.f, 0.f};
    float Pa[4] = {0.f, 0.f, 0.f, 0.f};

    for (int t = 0; t < TTILES; t++) {
        uint32_t bufB = sb + ((t & 1) ? SOFF_B1 : SOFF_B0);
        // prefetch next B tile into the other buffer
        if (t + 1 < TTILES) {
            uint32_t nbuf = sb + (((t + 1) & 1) ? SOFF_B1 : SOFF_B0);
            load_tile(nbuf, split_base + (t + 1) * 128, tid);
            CP_COMMIT();
        }
        // stage this tile's column labels
        if (tid < 128) lbl_s[tid] = g_lbl[split_base + t * 128 + tid];
        if (t + 1 < TTILES) { CP_WAIT1(); } else { CP_WAIT0(); }
        __syncthreads();

        // ---- MMA: 128x128 += A(128x256) * B(128x256)^T ----
        float acc[2][8][4];
        #pragma unroll
        for (int mf = 0; mf < 2; mf++)
            #pragma unroll
            for (int j = 0; j < 8; j++)
                #pragma unroll
                for (int r = 0; r < 4; r++) acc[mf][j][r] = 0.f;

        uint32_t bAddr = bufB + bOff;
        #pragma unroll
        for (int ks = 0; ks < 16; ks++) {
            uint32_t a[2][4], b[4][4];
            ldsm4(a[0], aAddr + ks * 32);
            ldsm4(a[1], aAddr + 16 * ROWB + ks * 32);
            #pragma unroll
            for (int jj = 0; jj < 4; jj++)
                ldsm4(b[jj], bAddr + jj * (16 * ROWB) + ks * 32);
            #pragma unroll
            for (int mf = 0; mf < 2; mf++)
                #pragma unroll
                for (int jj = 0; jj < 4; jj++) {
                    mma16816(acc[mf][2 * jj + 0], a[mf], &b[jj][0]);
                    mma16816(acc[mf][2 * jj + 1], a[mf], &b[jj][2]);
                }
        }

        // ---- Epilogue: exp-sum + label-masked positive sum ----
        bool dt = (split_base + t * 128) == row_base;  // tile contains the diagonal?
        #pragma unroll
        for (int j = 0; j < 8; j++) {
            int c2 = warpN * 64 + j * 8 + 2 * (lid & 3);  // col-in-tile of value pair
            int2 lp = *(const int2*)&lbl_s[c2];
            int cg0 = split_base + t * 128 + c2;
            #pragma unroll
            for (int mf = 0; mf < 2; mf++) {
                #pragma unroll
                for (int hi = 0; hi < 2; hi++) {
                    int idx = mf * 2 + hi;
                    float d0 = acc[mf][j][hi * 2 + 0];
                    float d1 = acc[mf][j][hi * 2 + 1];
                    Sa[idx] += ex2f(fmaf(d0, K_EX2, -K_EX2));
                    Sa[idx] += ex2f(fmaf(d1, K_EX2, -K_EX2));
                    bool m0 = (lp.x == myl[idx]);
                    bool m1 = (lp.y == myl[idx]);
                    if (dt) {
                        m0 = m0 && (cg0 != rowg[idx]);
                        m1 = m1 && (cg0 + 1 != rowg[idx]);
                    }
                    if (m0) Pa[idx] += d0;
                    if (m1) Pa[idx] += d1;
                }
            }
        }
        __syncthreads();
    }

    // Reduce S/P across the 4 lanes of each quad (they share rows, cover cols)
    int slot = split * 2 + warpN;
    #pragma unroll
    for (int idx = 0; idx < 4; idx++) {
        float s = Sa[idx], p = Pa[idx];
        s += __shfl_xor_sync(0xffffffffu, s, 1);
        s += __shfl_xor_sync(0xffffffffu, s, 2);
        p += __shfl_xor_sync(0xffffffffu, p, 1);
        p += __shfl_xor_sync(0xffffffffu, p, 2);
        if ((lid & 3) == 0) {
            g_S[slot][rowg[idx]] = s;
            g_P[slot][rowg[idx]] = p;
        }
    }
}

// ============================================================================
// Kernel 5: final reduction -> scalar mean loss
// ============================================================================
__global__ void finalize_kernel(float* __restrict__ out) {
    int tid = threadIdx.x;  // 1024 threads
    float acc = 0.f;
    for (int i = tid; i < NROWS; i += 1024) {
        float S = g_S[0][i] + g_S[1][i] + g_S[2][i] + g_S[3][i];
        float P = g_P[0][i] + g_P[1][i] + g_P[2][i] + g_P[3][i];
        int cnt = g_hist[g_lbl[i]] - 1;
        if (cnt > 0)
            acc += TEMP_INV + logf(S) - (P * TEMP_INV) / (float)cnt;
    }
    #pragma unroll
    for (int o = 16; o; o >>= 1) acc += __shfl_xor_sync(0xffffffffu, acc, o);
    __shared__ float ws[32];
    if ((tid & 31) == 0) ws[tid >> 5] = acc;
    __syncthreads();
    if (tid < 32) {
        float v = ws[tid];
        #pragma unroll
        for (int o = 16; o; o >>= 1) v += __shfl_xor_sync(0xffffffffu, v, o);
        if (tid == 0) out[0] = v / (float)NROWS;
    }
}

// ============================================================================
// Launch
// ============================================================================
extern "C" void kernel_launch(void* const* d_in, const int* in_sizes, int n_in,
                              void* d_out, int out_size) {
    const float* emb;
    const void* lab;
    if (in_sizes[0] == NROWS * DIMK) {
        emb = (const float*)d_in[0];
        lab = d_in[1];
    } else {
        emb = (const float*)d_in[1];
        lab = d_in[0];
    }

    cudaFuncSetAttribute(gemm_kernel, cudaFuncAttributeMaxDynamicSharedMemorySize, SMEM_TOTAL);

    zero_kernel<<<1, 1024>>>();
    detect_kernel<<<1, 256>>>((const int*)lab);
    prep_kernel<<<NROWS, 256>>>(emb, lab);
    gemm_kernel<<<dim3(NSPLIT, 64), 256, SMEM_TOTAL>>>();
    finalize_kernel<<<1, 1024>>>((float*)d_out);
}

// round 3
// speedup vs baseline: 1.3361x; 1.3361x over previous
#include <cuda_runtime.h>
#include <cuda_bf16.h>
#include <stdint.h>

// ============================================================================
// Problem constants
// ============================================================================
#define NROWS 8192
#define DIMK  256
#define NLBL  1024
#define NSPLIT 2                       // column splits
#define COLS_PER_CTA (NROWS / NSPLIT)  // 4096
#define TTILES (COLS_PER_CTA / 128)    // 32
#define TEMP_INV 14.285714285714286f   // 1/0.07
// exp((d-1)/T) = 2^(d*K - K), K = (1/T)*log2(e)
#define K_EX2 20.609929191666664f

// ============================================================================
// Device scratch (no allocation allowed)
// ============================================================================
__device__ __align__(128) __nv_bfloat16 g_en[NROWS * DIMK];  // normalized rows, bf16
__device__ int   g_lbl[NROWS];
__device__ int   g_hist[NLBL];
__device__ int   g_is64;
__device__ float g_S[4 * NSPLIT][NROWS];  // partial exp-sums per (split, warpN)
__device__ float g_P[4 * NSPLIT][NROWS];  // partial positive-sim sums

// ============================================================================
// PTX helpers (baseline sm_80+ only — target is compute_103 WITHOUT 'a')
// ============================================================================
__device__ __forceinline__ uint32_t smem_u32(const void* p) {
    uint32_t a;
    asm("{ .reg .u64 t; cvta.to.shared.u64 t, %1; cvt.u32.u64 %0, t; }" : "=r"(a) : "l"(p));
    return a;
}

__device__ __forceinline__ void cp16(uint32_t dst, const void* src) {
    asm volatile("cp.async.cg.shared.global [%0], [%1], 16;" :: "r"(dst), "l"(src));
}
#define CP_COMMIT() asm volatile("cp.async.commit_group;" ::: "memory")
#define CP_WAIT1()  asm volatile("cp.async.wait_group 1;" ::: "memory")
#define CP_WAIT0()  asm volatile("cp.async.wait_group 0;" ::: "memory")

__device__ __forceinline__ void ldsm4(uint32_t* r, uint32_t addr) {
    asm volatile("ldmatrix.sync.aligned.m8n8.x4.shared.b16 {%0,%1,%2,%3}, [%4];"
        : "=r"(r[0]), "=r"(r[1]), "=r"(r[2]), "=r"(r[3]) : "r"(addr));
}

__device__ __forceinline__ void mma16816(float* d, const uint32_t* a, const uint32_t* b) {
    asm volatile(
        "mma.sync.aligned.m16n8k16.row.col.f32.bf16.bf16.f32 "
        "{%0,%1,%2,%3}, {%4,%5,%6,%7}, {%8,%9}, {%0,%1,%2,%3};"
        : "+f"(d[0]), "+f"(d[1]), "+f"(d[2]), "+f"(d[3])
        : "r"(a[0]), "r"(a[1]), "r"(a[2]), "r"(a[3]), "r"(b[0]), "r"(b[1]));
}

__device__ __forceinline__ float ex2f(float x) {
    float e;
    asm("ex2.approx.f32 %0, %1;" : "=f"(e) : "f"(x));
    return e;
}

// ============================================================================
// SMEM layout (padded K-major tiles: 128 rows x 264 bf16 -> 528 B row stride)
// ============================================================================
#define ROWB   528
#define TILEB  (128 * ROWB)                // 67584
#define SOFF_A   0
#define SOFF_B0  TILEB
#define SOFF_B1  (2 * TILEB)
#define SMEM_TOTAL (3 * TILEB)             // 202752

// Fill one 128-row x 256-col bf16 tile via cp.async. 512 threads, 4096 chunks.
__device__ __forceinline__ void load_tile(uint32_t dst_base, int grow_base, int tid) {
    #pragma unroll
    for (int i = 0; i < 8; i++) {
        int c = tid + i * 512;     // 0..4095
        int r = c >> 5;            // row
        int q = c & 31;            // 16B chunk
        cp16(dst_base + r * ROWB + q * 16,
             (const void*)(g_en + (size_t)(grow_base + r) * DIMK + q * 8));
    }
}

// ============================================================================
// Kernel 1: zero histogram
// ============================================================================
__global__ void zero_kernel() {
    if (threadIdx.x < NLBL) g_hist[threadIdx.x] = 0;
}

// ============================================================================
// Kernel 2: detect labels dtype (int64 vs int32)
// ============================================================================
__global__ void detect_kernel(const int* lab32) {
    __shared__ int any;
    if (threadIdx.x == 0) any = 0;
    __syncthreads();
    for (int i = threadIdx.x; i < 4096; i += blockDim.x)
        if (lab32[2 * i + 1] != 0) any = 1;  // benign race
    __syncthreads();
    if (threadIdx.x == 0) g_is64 = (any == 0) ? 1 : 0;
}

// ============================================================================
// Kernel 3: normalize rows -> bf16, labels -> int32, histogram
// ============================================================================
__global__ void prep_kernel(const float* __restrict__ emb, const void* __restrict__ labels) {
    int row = blockIdx.x;
    int tid = threadIdx.x;  // 256 threads = 1 per element
    float v = emb[(size_t)row * DIMK + tid];
    float ss = v * v;
    #pragma unroll
    for (int o = 16; o; o >>= 1) ss += __shfl_xor_sync(0xffffffffu, ss, o);
    __shared__ float ws[8];
    if ((tid & 31) == 0) ws[tid >> 5] = ss;
    __syncthreads();
    float tot = ws[0] + ws[1] + ws[2] + ws[3] + ws[4] + ws[5] + ws[6] + ws[7];
    float inv = 1.0f / fmaxf(sqrtf(tot), 1e-12f);
    g_en[(size_t)row * DIMK + tid] = __float2bfloat16(v * inv);
    if (tid == 0) {
        int l = g_is64 ? (int)((const long long*)labels)[row] : ((const int*)labels)[row];
        g_lbl[row] = l;
        atomicAdd(&g_hist[l], 1);
    }
}

// ============================================================================
// Kernel 4: fused bf16 mma.sync GEMM, 512 threads = 16 warps (4M x 4N),
// warp tile 32x32, double-buffered accumulators: epilogue of tile t-1 is
// interleaved into the MMA loop of tile t (MUFU rides on tensor phase).
// ============================================================================
typedef float Acc[2][4][4];  // [mf][j][r]

template <bool HAS_PREV>
__device__ __forceinline__ void do_tile(
    int t, uint32_t sb, int tid, int lid, int warpN,
    int split_base, int row_base,
    uint32_t aAddr, uint32_t bOff,
    Acc& cur, Acc& prev,
    float* Sa, float* Pa, const int* myl, const int* rowg,
    int* lpx, int* lpy, int& prev_tb, int& prev_dt)
{
    uint32_t bufB = sb + ((t & 1) ? SOFF_B1 : SOFF_B0);
    // prefetch next tile's B into the other buffer (freed by prior tile-end barrier)
    if (t + 1 < TTILES) {
        uint32_t nbuf = sb + (((t + 1) & 1) ? SOFF_B1 : SOFF_B0);
        load_tile(nbuf, split_base + (t + 1) * 128, tid);
        CP_COMMIT();
        CP_WAIT1();
    } else {
        CP_WAIT0();
    }
    __syncthreads();  // B(t) visible to all warps

    #pragma unroll
    for (int mf = 0; mf < 2; mf++)
        #pragma unroll
        for (int j = 0; j < 4; j++)
            #pragma unroll
            for (int r = 0; r < 4; r++) cur[mf][j][r] = 0.f;

    int coff = warpN * 32 + 2 * (lid & 3);  // column offset base (j*8 added below)
    uint32_t bAddr = bufB + bOff;

    #pragma unroll
    for (int ks = 0; ks < 16; ks++) {
        uint32_t a[2][4], b[2][4];
        ldsm4(a[0], aAddr + ks * 32);
        ldsm4(a[1], aAddr + 16 * ROWB + ks * 32);
        ldsm4(b[0], bAddr + ks * 32);
        ldsm4(b[1], bAddr + 16 * ROWB + ks * 32);
        #pragma unroll
        for (int mf = 0; mf < 2; mf++)
            #pragma unroll
            for (int jj = 0; jj < 2; jj++) {
                mma16816(cur[mf][2 * jj + 0], a[mf], &b[jj][0]);
                mma16816(cur[mf][2 * jj + 1], a[mf], &b[jj][2]);
            }
        if (HAS_PREV) {
            // interleaved epilogue: 2 values of previous tile's acc per ks step
            #pragma unroll
            for (int u = 0; u < 2; u++) {
                const int v = 2 * ks + u;
                const int mf = v >> 4, j = (v >> 2) & 3, r = v & 3;
                const int hi = r >> 1, lo = r & 1;
                const int idx = mf * 2 + hi;
                float d = prev[mf][j][r];
                Sa[idx] += ex2f(fmaf(d, K_EX2, -K_EX2));
                int lj = lo ? lpy[j] : lpx[j];
                int cg = prev_tb + coff + j * 8 + lo;
                bool m = (lj == myl[idx]) && (!prev_dt || cg != rowg[idx]);
                if (m) Pa[idx] += d;
            }
        }
    }

    // stage this tile's column labels for its epilogue (next iteration)
    int tb = split_base + t * 128;
    #pragma unroll
    for (int j = 0; j < 4; j++) {
        int2 lp = __ldg((const int2*)(g_lbl + tb + warpN * 32 + j * 8 + 2 * (lid & 3)));
        lpx[j] = lp.x;
        lpy[j] = lp.y;
    }
    prev_tb = tb;
    prev_dt = (tb == row_base);

    __syncthreads();  // all warps done reading both buffers for this tile
}

__global__ void __launch_bounds__(512, 1) gemm_kernel() {
    extern __shared__ char smem[];
    uint32_t sb = smem_u32(smem);
    int tid = threadIdx.x, wid = tid >> 5, lid = tid & 31;
    int warpM = wid & 3, warpN = wid >> 2;  // 4 x 4 warp grid, 32x32 warp tiles
    int split = blockIdx.x, rtile = blockIdx.y;
    int row_base = rtile * 128;
    int split_base = split * COLS_PER_CTA;

    // per-lane fixed rows: row_base + warpM*32 + mf*16 + hi*8 + lid/4
    int rowg[4], myl[4];
    #pragma unroll
    for (int idx = 0; idx < 4; idx++) {
        int mf = idx >> 1, hi = idx & 1;
        rowg[idx] = row_base + warpM * 32 + mf * 16 + hi * 8 + (lid >> 2);
        myl[idx] = __ldg(&g_lbl[rowg[idx]]);
    }

    // ldmatrix per-lane base addresses
    uint32_t aAddr = sb + SOFF_A
        + (uint32_t)(warpM * 32 + (lid & 7) + ((lid >> 3) & 1) * 8) * ROWB
        + ((lid >> 4) & 1) * 16;
    uint32_t bOff =
        (uint32_t)(warpN * 32 + (lid & 7) + ((lid >> 4) & 1) * 8) * ROWB
        + ((lid >> 3) & 1) * 16;

    // Prologue: A tile + B tile 0 as one cp.async group
    load_tile(sb + SOFF_A, row_base, tid);
    load_tile(sb + SOFF_B0, split_base, tid);
    CP_COMMIT();

    Acc acc0, acc1;
    float Sa[4] = {0.f, 0.f, 0.f, 0.f};
    float Pa[4] = {0.f, 0.f, 0.f, 0.f};
    int lpx[4], lpy[4];
    int prev_tb = 0, prev_dt = 0;

    do_tile<false>(0, sb, tid, lid, warpN, split_base, row_base, aAddr, bOff,
                   acc0, acc1, Sa, Pa, myl, rowg, lpx, lpy, prev_tb, prev_dt);
    for (int tt = 0; tt < 15; tt++) {
        do_tile<true>(1 + 2 * tt, sb, tid, lid, warpN, split_base, row_base, aAddr, bOff,
                      acc1, acc0, Sa, Pa, myl, rowg, lpx, lpy, prev_tb, prev_dt);
        do_tile<true>(2 + 2 * tt, sb, tid, lid, warpN, split_base, row_base, aAddr, bOff,
                      acc0, acc1, Sa, Pa, myl, rowg, lpx, lpy, prev_tb, prev_dt);
    }
    do_tile<true>(31, sb, tid, lid, warpN, split_base, row_base, aAddr, bOff,
                  acc1, acc0, Sa, Pa, myl, rowg, lpx, lpy, prev_tb, prev_dt);

    // tail epilogue for tile 31 (acc1), labels in lpx/lpy, tb/dt in prev_*
    {
        int coff = warpN * 32 + 2 * (lid & 3);
        #pragma unroll
        for (int v = 0; v < 32; v++) {
            const int mf = v >> 4, j = (v >> 2) & 3, r = v & 3;
            const int hi = r >> 1, lo = r & 1;
            const int idx = mf * 2 + hi;
            float d = acc1[mf][j][r];
            Sa[idx] += ex2f(fmaf(d, K_EX2, -K_EX2));
            int lj = lo ? lpy[j] : lpx[j];
            int cg = prev_tb + coff + j * 8 + lo;
            bool m = (lj == myl[idx]) && (!prev_dt || cg != rowg[idx]);
            if (m) Pa[idx] += d;
        }
    }

    // quad reduction (lanes lid&3 share rows, cover columns) and store
    int slot = split * 4 + warpN;
    #pragma unroll
    for (int idx = 0; idx < 4; idx++) {
        float s = Sa[idx], p = Pa[idx];
        s += __shfl_xor_sync(0xffffffffu, s, 1);
        s += __shfl_xor_sync(0xffffffffu, s, 2);
        p += __shfl_xor_sync(0xffffffffu, p, 1);
        p += __shfl_xor_sync(0xffffffffu, p, 2);
        if ((lid & 3) == 0) {
            g_S[slot][rowg[idx]] = s;
            g_P[slot][rowg[idx]] = p;
        }
    }
}

// ============================================================================
// Kernel 5: final reduction -> scalar mean loss
// ============================================================================
__global__ void finalize_kernel(float* __restrict__ out) {
    int tid = threadIdx.x;  // 1024 threads
    float acc = 0.f;
    for (int i = tid; i < NROWS; i += 1024) {
        float S = 0.f, P = 0.f;
        #pragma unroll
        for (int s = 0; s < 4 * NSPLIT; s++) {
            S += g_S[s][i];
            P += g_P[s][i];
        }
        int cnt = g_hist[g_lbl[i]] - 1;
        if (cnt > 0)
            acc += TEMP_INV + logf(S) - (P * TEMP_INV) / (float)cnt;
    }
    #pragma unroll
    for (int o = 16; o; o >>= 1) acc += __shfl_xor_sync(0xffffffffu, acc, o);
    __shared__ float ws[32];
    if ((tid & 31) == 0) ws[tid >> 5] = acc;
    __syncthreads();
    if (tid < 32) {
        float v = ws[tid];
        #pragma unroll
        for (int o = 16; o; o >>= 1) v += __shfl_xor_sync(0xffffffffu, v, o);
        if (tid == 0) out[0] = v / (float)NROWS;
    }
}

// ============================================================================
// Launch
// ============================================================================
extern "C" void kernel_launch(void* const* d_in, const int* in_sizes, int n_in,
                              void* d_out, int out_size) {
    const float* emb;
    const void* lab;
    if (in_sizes[0] == NROWS * DIMK) {
        emb = (const float*)d_in[0];
        lab = d_in[1];
    } else {
        emb = (const float*)d_in[1];
        lab = d_in[0];
    }

    cudaFuncSetAttribute(gemm_kernel, cudaFuncAttributeMaxDynamicSharedMemorySize, SMEM_TOTAL);

    zero_kernel<<<1, 1024>>>();
    detect_kernel<<<1, 256>>>((const int*)lab);
    prep_kernel<<<NROWS, 256>>>(emb, lab);
    gemm_kernel<<<dim3(NSPLIT, 64), 512, SMEM_TOTAL>>>();
    finalize_kernel<<<1, 1024>>>((float*)d_out);
}